// round 11
// baseline (speedup 1.0000x reference)
#include <cuda_runtime.h>
#include <cuda_bf16.h>
#include <cstdint>
#include <cstddef>

// Problem constants
#define NN   32768
#define EE   16384
#define DDN  4
#define KKN  8
#define HID  128
#define EDIM 64
#define NHD  8
#define LLK  32

// -------------------- scratch (device globals; no allocations) --------------
__device__ float g_Wc[3 * 128 * 128];   // Wq*Wlin, Wk*Wlin, Wv*Wlin
__device__ float g_We[128 * 64];        // Wk*W_edge
__device__ float g_Q[(size_t)NN * 128];
__device__ float g_KWh[(size_t)NN * 128];
__device__ float g_VWh[(size_t)NN * 128];
__device__ float g_KWe[(size_t)EE * 128];
__device__ float g_CTX[(size_t)NN * 128];

// -------------------- K0: weight folding (fp32) ------------------------------
__global__ void combine_w(const float* __restrict__ Wlin,
                          const float* __restrict__ Wedge,
                          const float* __restrict__ Wq,
                          const float* __restrict__ Wk,
                          const float* __restrict__ Wv)
{
    int o = blockIdx.x, mat = blockIdx.y, i = threadIdx.x;
    if (mat < 3) {
        const float* Wt = (mat == 0) ? Wq : ((mat == 1) ? Wk : Wv);
        float s = 0.f;
        #pragma unroll 8
        for (int j = 0; j < 128; j++) s = fmaf(Wt[o * 128 + j], Wlin[j * 128 + i], s);
        g_Wc[((size_t)mat * 128 + o) * 128 + i] = s;
    } else if (i < 64) {
        float s = 0.f;
        #pragma unroll 8
        for (int j = 0; j < 128; j++) s = fmaf(Wk[o * 128 + j], Wedge[j * 64 + i], s);
        g_We[o * 64 + i] = s;
    }
}

// -------------------- HMMA (mma.sync) split-bf16 GEMM ------------------------
// out_m[128, 128] = act(A[128, KA] @ W_m[128, KA]^T + bias_m),  m < NMAT
// D = Ahi*Bhi + Ahi*Blo + Alo*Bhi  (fp32 register accumulators).
// 256 threads; warp w: rows (w&3)*32..+32, cols (w>>2)*64..+64.
// SMEM u32 layout per buffer: [128 rows][SW] where SW = KA/2+4 (stride ≡ 4 mod 32
// -> the (8 rows x 4 kpairs) fragment read pattern hits 32 distinct banks).

__device__ __forceinline__ void mma16816(float* d, const uint32_t* a,
                                         uint32_t b0, uint32_t b1)
{
    asm volatile(
        "mma.sync.aligned.m16n8k16.row.col.f32.bf16.bf16.f32 "
        "{%0,%1,%2,%3}, {%4,%5,%6,%7}, {%8,%9}, {%0,%1,%2,%3};"
        : "+f"(d[0]), "+f"(d[1]), "+f"(d[2]), "+f"(d[3])
        : "r"(a[0]), "r"(a[1]), "r"(a[2]), "r"(a[3]), "r"(b0), "r"(b1));
}

template <int KA>
__device__ __forceinline__ void stage_split(const float* __restrict__ src,
                                            uint32_t* __restrict__ hi,
                                            uint32_t* __restrict__ lo, int tid)
{
    constexpr int SW = KA / 2 + 4;
    constexpr int QUADS = 128 * KA / 4;
    #pragma unroll 4
    for (int idx = tid; idx < QUADS; idx += 256) {
        int row = idx / (KA / 4);
        int q   = idx % (KA / 4);
        float4 v = *(const float4*)(src + (size_t)row * KA + q * 4);
        __nv_bfloat16 h0 = __float2bfloat16(v.x);
        __nv_bfloat16 h1 = __float2bfloat16(v.y);
        __nv_bfloat16 h2 = __float2bfloat16(v.z);
        __nv_bfloat16 h3 = __float2bfloat16(v.w);
        __nv_bfloat16 l0 = __float2bfloat16(v.x - __bfloat162float(h0));
        __nv_bfloat16 l1 = __float2bfloat16(v.y - __bfloat162float(h1));
        __nv_bfloat16 l2 = __float2bfloat16(v.z - __bfloat162float(h2));
        __nv_bfloat16 l3 = __float2bfloat16(v.w - __bfloat162float(h3));
        int base = row * SW + 2 * q;
        hi[base + 0] = ((uint32_t)__bfloat16_as_ushort(h1) << 16) | __bfloat16_as_ushort(h0);
        hi[base + 1] = ((uint32_t)__bfloat16_as_ushort(h3) << 16) | __bfloat16_as_ushort(h2);
        lo[base + 0] = ((uint32_t)__bfloat16_as_ushort(l1) << 16) | __bfloat16_as_ushort(l0);
        lo[base + 1] = ((uint32_t)__bfloat16_as_ushort(l3) << 16) | __bfloat16_as_ushort(l2);
    }
}

template <int KA, int NMAT, bool RELU>
__global__ void __launch_bounds__(256)
gemm_mma(const float* __restrict__ A, const float* __restrict__ W,
         const float* __restrict__ b0, const float* __restrict__ b1,
         const float* __restrict__ b2,
         float* __restrict__ o0, float* __restrict__ o1, float* __restrict__ o2)
{
    constexpr int SW  = KA / 2 + 4;      // u32 row stride
    constexpr int BUF = 128 * SW;        // u32 per buffer
    constexpr int NSTEP = KA / 16;

    extern __shared__ uint32_t smem[];
    uint32_t* sAhi = smem;
    uint32_t* sAlo = smem + BUF;
    uint32_t* sBhi = smem + 2 * BUF;
    uint32_t* sBlo = smem + 3 * BUF;

    const int tid  = threadIdx.x;
    const int w    = tid >> 5;
    const int lane = tid & 31;
    const int g    = lane >> 2;
    const int q    = lane & 3;
    const int bm   = blockIdx.x * 128;
    const int mrow = (w & 3) * 32;       // warp row base within tile
    const int ncol = (w >> 2) * 64;      // warp col base within tile

    stage_split<KA>(A + (size_t)bm * KA, sAhi, sAlo, tid);
    __syncthreads();

    for (int m = 0; m < NMAT; m++) {
        stage_split<KA>(W + (size_t)m * 128 * KA, sBhi, sBlo, tid);
        __syncthreads();

        float d[2][8][4];
        #pragma unroll
        for (int mi = 0; mi < 2; mi++)
            #pragma unroll
            for (int ni = 0; ni < 8; ni++)
                #pragma unroll
                for (int c = 0; c < 4; c++) d[mi][ni][c] = 0.f;

        #pragma unroll
        for (int k = 0; k < NSTEP; k++) {
            const int kp = k * 8;
            uint32_t ah[2][4], al[2][4];
            #pragma unroll
            for (int mi = 0; mi < 2; mi++) {
                int r0 = (mrow + mi * 16 + g) * SW + kp + q;
                int r1 = r0 + 8 * SW;
                ah[mi][0] = sAhi[r0];     ah[mi][1] = sAhi[r1];
                ah[mi][2] = sAhi[r0 + 4]; ah[mi][3] = sAhi[r1 + 4];
                al[mi][0] = sAlo[r0];     al[mi][1] = sAlo[r1];
                al[mi][2] = sAlo[r0 + 4]; al[mi][3] = sAlo[r1 + 4];
            }
            #pragma unroll
            for (int ni = 0; ni < 8; ni++) {
                int cb = (ncol + ni * 8 + g) * SW + kp + q;
                uint32_t bh0 = sBhi[cb], bh1 = sBhi[cb + 4];
                uint32_t bl0 = sBlo[cb], bl1 = sBlo[cb + 4];
                #pragma unroll
                for (int mi = 0; mi < 2; mi++) {
                    mma16816(d[mi][ni], ah[mi], bh0, bh1);
                    mma16816(d[mi][ni], ah[mi], bl0, bl1);
                    mma16816(d[mi][ni], al[mi], bh0, bh1);
                }
            }
        }

        // epilogue: C frag -> (row g / g+8, cols 2q, 2q+1)
        const float* bias = (m == 0) ? b0 : ((m == 1) ? b1 : b2);
        float* outp       = (m == 0) ? o0 : ((m == 1) ? o1 : o2);
        #pragma unroll
        for (int mi = 0; mi < 2; mi++) {
            int rA = bm + mrow + mi * 16 + g;
            #pragma unroll
            for (int ni = 0; ni < 8; ni++) {
                int c = ncol + ni * 8 + q * 2;
                float bx = bias ? bias[c] : 0.f;
                float by = bias ? bias[c + 1] : 0.f;
                float2 v0, v1;
                v0.x = d[mi][ni][0] + bx;  v0.y = d[mi][ni][1] + by;
                v1.x = d[mi][ni][2] + bx;  v1.y = d[mi][ni][3] + by;
                if (RELU) {
                    v0.x = fmaxf(v0.x, 0.f); v0.y = fmaxf(v0.y, 0.f);
                    v1.x = fmaxf(v1.x, 0.f); v1.y = fmaxf(v1.y, 0.f);
                }
                *(float2*)(outp + (size_t)rA * 128 + c)       = v0;
                *(float2*)(outp + (size_t)(rA + 8) * 128 + c) = v1;
            }
        }
        __syncthreads();   // all warps done reading B before restage
    }
}

// -------------------- attention: one warp per node ---------------------------
__global__ void __launch_bounds__(256)
attn_kernel(const int* __restrict__ node_edges,
            const int* __restrict__ edge_nodes)
{
    __shared__ float sc[8][8][32];
    const unsigned FULL = 0xffffffffu;
    int t = threadIdx.x & 31;
    int w = threadIdx.x >> 5;
    int n = blockIdx.x * 8 + w;

    int d = t >> 3, j = t & 7;
    int e = node_edges[n * DDN + d];
    int u = edge_nodes[e * KKN + j];

    float4 q = ((const float4*)(g_Q + (size_t)n * 128))[t];
    int g = t >> 2;

    float es[4];
    #pragma unroll
    for (int dd = 0; dd < 4; dd++) {
        int ee = __shfl_sync(FULL, e, dd * 8);
        float4 kf = ((const float4*)(g_KWe + (size_t)ee * 128))[t];
        float p = fmaf(q.x, kf.x, fmaf(q.y, kf.y, fmaf(q.z, kf.z, q.w * kf.w)));
        p += __shfl_xor_sync(FULL, p, 1);
        p += __shfl_xor_sync(FULL, p, 2);
        es[dd] = p;
    }

    #pragma unroll
    for (int l = 0; l < 32; l++) {
        int uu = __shfl_sync(FULL, u, l);
        float4 kf = ((const float4*)(g_KWh + (size_t)uu * 128))[t];
        float p = fmaf(q.x, kf.x, fmaf(q.y, kf.y, fmaf(q.z, kf.z, q.w * kf.w)));
        p += __shfl_xor_sync(FULL, p, 1);
        p += __shfl_xor_sync(FULL, p, 2);
        if ((t & 3) == 0) sc[w][g][l] = (p + es[l >> 3]) * 0.25f;
    }
    __syncwarp();

    {
        int r = t & 3;
        float vv[8];
        float m = -1e30f;
        #pragma unroll
        for (int i = 0; i < 8; i++) { vv[i] = sc[w][g][r + i * 4]; m = fmaxf(m, vv[i]); }
        m = fmaxf(m, __shfl_xor_sync(FULL, m, 1));
        m = fmaxf(m, __shfl_xor_sync(FULL, m, 2));
        float s = 0.f;
        #pragma unroll
        for (int i = 0; i < 8; i++) { vv[i] = __expf(vv[i] - m); s += vv[i]; }
        s += __shfl_xor_sync(FULL, s, 1);
        s += __shfl_xor_sync(FULL, s, 2);
        float inv = 1.0f / s;
        #pragma unroll
        for (int i = 0; i < 8; i++) sc[w][g][r + i * 4] = vv[i] * inv;
    }
    __syncwarp();

    float4 acc = make_float4(0.f, 0.f, 0.f, 0.f);
    #pragma unroll
    for (int l = 0; l < 32; l++) {
        int uu = __shfl_sync(FULL, u, l);
        float a = sc[w][g][l];
        float4 vf = ((const float4*)(g_VWh + (size_t)uu * 128))[t];
        acc.x = fmaf(a, vf.x, acc.x);
        acc.y = fmaf(a, vf.y, acc.y);
        acc.z = fmaf(a, vf.z, acc.z);
        acc.w = fmaf(a, vf.w, acc.w);
    }
    ((float4*)(g_CTX + (size_t)n * 128))[t] = acc;
}

// -------------------- launch -------------------------------------------------
extern "C" void kernel_launch(void* const* d_in, const int* in_sizes, int n_in,
                              void* d_out, int out_size)
{
    const float* x          = (const float*)d_in[0];
    const float* edge_attr  = (const float*)d_in[1];
    const int*   node_edges = (const int*)  d_in[2];
    const int*   edge_nodes = (const int*)  d_in[3];
    const float* W_lin      = (const float*)d_in[4];
    const float* W_edge     = (const float*)d_in[5];
    const float* Wq         = (const float*)d_in[6];
    const float* Wk         = (const float*)d_in[7];
    const float* Wv         = (const float*)d_in[8];
    const float* bq         = (const float*)d_in[9];
    const float* bk         = (const float*)d_in[10];
    const float* bv         = (const float*)d_in[11];
    const float* Wo         = (const float*)d_in[12];
    const float* bo         = (const float*)d_in[13];
    float*       out        = (float*)d_out;

    int Nn = in_sizes[0] / HID;    // 32768
    int En = in_sizes[1] / EDIM;   // 16384

    float *pWc, *pWe, *pQ, *pKWh, *pVWh, *pKWe, *pCTX;
    cudaGetSymbolAddress((void**)&pWc,  g_Wc);
    cudaGetSymbolAddress((void**)&pWe,  g_We);
    cudaGetSymbolAddress((void**)&pQ,   g_Q);
    cudaGetSymbolAddress((void**)&pKWh, g_KWh);
    cudaGetSymbolAddress((void**)&pVWh, g_VWh);
    cudaGetSymbolAddress((void**)&pKWe, g_KWe);
    cudaGetSymbolAddress((void**)&pCTX, g_CTX);

    // dynamic SMEM: 4 buffers of 128*(KA/2+4) u32
    const int SM128 = 4 * 128 * (128 / 2 + 4) * 4;   // 139264 B
    const int SM64  = 4 * 128 * (64 / 2 + 4) * 4;    //  73728 B
    cudaFuncSetAttribute(gemm_mma<128, 3, false>, cudaFuncAttributeMaxDynamicSharedMemorySize, SM128);
    cudaFuncSetAttribute(gemm_mma<128, 1, true>,  cudaFuncAttributeMaxDynamicSharedMemorySize, SM128);
    cudaFuncSetAttribute(gemm_mma<64, 1, false>,  cudaFuncAttributeMaxDynamicSharedMemorySize, SM64);

    // K0: fold weights
    combine_w<<<dim3(128, 4), 128>>>(W_lin, W_edge, Wq, Wk, Wv);

    // K1: fused node projections  Q | KWh | VWh  (A staged once)
    gemm_mma<128, 3, false><<<Nn / 128, 256, SM128>>>(
        x, pWc, bq, nullptr, bv, pQ, pKWh, pVWh);

    // K2: edge projection  KWe = edge_attr @ (Wk W_edge)^T + bk
    gemm_mma<64, 1, false><<<En / 128, 256, SM64>>>(
        edge_attr, pWe, bk, nullptr, nullptr, pKWe, nullptr, nullptr);

    // K3: attention -> ctx
    attn_kernel<<<Nn / 8, 256>>>(node_edges, edge_nodes);

    // K4: out = relu(ctx @ Wo^T + bo)
    gemm_mma<128, 1, true><<<Nn / 128, 256, SM128>>>(
        pCTX, Wo, bo, nullptr, nullptr, out, nullptr, nullptr);
}

// round 12
// speedup vs baseline: 1.9191x; 1.9191x over previous
#include <cuda_runtime.h>
#include <cuda_bf16.h>
#include <cstdint>
#include <cstddef>

// Problem constants
#define NN   32768
#define EE   16384
#define DDN  4
#define KKN  8
#define HID  128
#define EDIM 64
#define NHD  8
#define LLK  32

#define QSCALE 4096.0f
#define INV_QSCALE (1.0f / 4096.0f)

// -------------------- scratch (device globals; no allocations) --------------
__device__ float g_Wc[3 * 128 * 128];       // Wq*Wlin, Wk*Wlin, Wv*Wlin
__device__ float g_We[128 * 64];            // Wk*W_edge
__device__ float g_Q[(size_t)NN * 128];     // fp32 queries
__device__ short g_KWh16[(size_t)NN * 128]; // int16 key-node table   (x4096)
__device__ short g_VWh16[(size_t)NN * 128]; // int16 value-node table (x4096)
__device__ short g_KWe16[(size_t)EE * 128]; // int16 key-edge table   (x4096)
__device__ float g_CTX[(size_t)NN * 128];

// -------------------- K0: weight folding (fp32) ------------------------------
__global__ void combine_w(const float* __restrict__ Wlin,
                          const float* __restrict__ Wedge,
                          const float* __restrict__ Wq,
                          const float* __restrict__ Wk,
                          const float* __restrict__ Wv)
{
    int o = blockIdx.x, mat = blockIdx.y, i = threadIdx.x;
    if (mat < 3) {
        const float* Wt = (mat == 0) ? Wq : ((mat == 1) ? Wk : Wv);
        float s = 0.f;
        #pragma unroll 8
        for (int j = 0; j < 128; j++) s = fmaf(Wt[o * 128 + j], Wlin[j * 128 + i], s);
        g_Wc[((size_t)mat * 128 + o) * 128 + i] = s;
    } else if (i < 64) {
        float s = 0.f;
        #pragma unroll 8
        for (int j = 0; j < 128; j++) s = fmaf(Wk[o * 128 + j], Wedge[j * 64 + i], s);
        g_We[o * 64 + i] = s;
    }
}

// -------------------- HMMA (mma.sync) split-bf16 GEMM ------------------------
// blockIdx.y = m (matrix index). out_m = act(A @ W_m^T + bias_m).
// D = Ahi*Bhi + Ahi*Blo + Alo*Bhi  (fp32 register accumulators).

__device__ __forceinline__ void mma16816(float* d, const uint32_t* a,
                                         uint32_t b0, uint32_t b1)
{
    asm volatile(
        "mma.sync.aligned.m16n8k16.row.col.f32.bf16.bf16.f32 "
        "{%0,%1,%2,%3}, {%4,%5,%6,%7}, {%8,%9}, {%0,%1,%2,%3};"
        : "+f"(d[0]), "+f"(d[1]), "+f"(d[2]), "+f"(d[3])
        : "r"(a[0]), "r"(a[1]), "r"(a[2]), "r"(a[3]), "r"(b0), "r"(b1));
}

template <int KA>
__device__ __forceinline__ void stage_split(const float* __restrict__ src,
                                            uint32_t* __restrict__ hi,
                                            uint32_t* __restrict__ lo, int tid)
{
    constexpr int SW = KA / 2 + 4;
    constexpr int QUADS = 128 * KA / 4;
    #pragma unroll 4
    for (int idx = tid; idx < QUADS; idx += 256) {
        int row = idx / (KA / 4);
        int q   = idx % (KA / 4);
        float4 v = *(const float4*)(src + (size_t)row * KA + q * 4);
        __nv_bfloat16 h0 = __float2bfloat16(v.x);
        __nv_bfloat16 h1 = __float2bfloat16(v.y);
        __nv_bfloat16 h2 = __float2bfloat16(v.z);
        __nv_bfloat16 h3 = __float2bfloat16(v.w);
        __nv_bfloat16 l0 = __float2bfloat16(v.x - __bfloat162float(h0));
        __nv_bfloat16 l1 = __float2bfloat16(v.y - __bfloat162float(h1));
        __nv_bfloat16 l2 = __float2bfloat16(v.z - __bfloat162float(h2));
        __nv_bfloat16 l3 = __float2bfloat16(v.w - __bfloat162float(h3));
        int base = row * SW + 2 * q;
        hi[base + 0] = ((uint32_t)__bfloat16_as_ushort(h1) << 16) | __bfloat16_as_ushort(h0);
        hi[base + 1] = ((uint32_t)__bfloat16_as_ushort(h3) << 16) | __bfloat16_as_ushort(h2);
        lo[base + 0] = ((uint32_t)__bfloat16_as_ushort(l1) << 16) | __bfloat16_as_ushort(l0);
        lo[base + 1] = ((uint32_t)__bfloat16_as_ushort(l3) << 16) | __bfloat16_as_ushort(l2);
    }
}

struct GemmArgs {
    const float* b0; const float* b1; const float* b2;
    void* o0; void* o1; void* o2;
    int i16mask;   // bit m set -> output m stored as int16 * QSCALE
};

template <int KA, bool RELU>
__global__ void __launch_bounds__(256)
gemm_mma(const float* __restrict__ A, const float* __restrict__ W, GemmArgs ga)
{
    constexpr int SW  = KA / 2 + 4;      // u32 row stride
    constexpr int BUF = 128 * SW;        // u32 per buffer
    constexpr int NSTEP = KA / 16;

    extern __shared__ uint32_t smem[];
    uint32_t* sAhi = smem;
    uint32_t* sAlo = smem + BUF;
    uint32_t* sBhi = smem + 2 * BUF;
    uint32_t* sBlo = smem + 3 * BUF;

    const int tid  = threadIdx.x;
    const int w    = tid >> 5;
    const int lane = tid & 31;
    const int g    = lane >> 2;
    const int q    = lane & 3;
    const int bm   = blockIdx.x * 128;
    const int m    = blockIdx.y;
    const int mrow = (w & 3) * 32;
    const int ncol = (w >> 2) * 64;

    stage_split<KA>(A + (size_t)bm * KA, sAhi, sAlo, tid);
    stage_split<KA>(W + (size_t)m * 128 * KA, sBhi, sBlo, tid);
    __syncthreads();

    float d[2][8][4];
    #pragma unroll
    for (int mi = 0; mi < 2; mi++)
        #pragma unroll
        for (int ni = 0; ni < 8; ni++)
            #pragma unroll
            for (int c = 0; c < 4; c++) d[mi][ni][c] = 0.f;

    #pragma unroll
    for (int k = 0; k < NSTEP; k++) {
        const int kp = k * 8;
        uint32_t ah[2][4], al[2][4];
        #pragma unroll
        for (int mi = 0; mi < 2; mi++) {
            int r0 = (mrow + mi * 16 + g) * SW + kp + q;
            int r1 = r0 + 8 * SW;
            ah[mi][0] = sAhi[r0];     ah[mi][1] = sAhi[r1];
            ah[mi][2] = sAhi[r0 + 4]; ah[mi][3] = sAhi[r1 + 4];
            al[mi][0] = sAlo[r0];     al[mi][1] = sAlo[r1];
            al[mi][2] = sAlo[r0 + 4]; al[mi][3] = sAlo[r1 + 4];
        }
        #pragma unroll
        for (int ni = 0; ni < 8; ni++) {
            int cb = (ncol + ni * 8 + g) * SW + kp + q;
            uint32_t bh0 = sBhi[cb], bh1 = sBhi[cb + 4];
            uint32_t bl0 = sBlo[cb], bl1 = sBlo[cb + 4];
            #pragma unroll
            for (int mi = 0; mi < 2; mi++) {
                mma16816(d[mi][ni], ah[mi], bh0, bh1);
                mma16816(d[mi][ni], ah[mi], bl0, bl1);
                mma16816(d[mi][ni], al[mi], bh0, bh1);
            }
        }
    }

    // epilogue
    const float* bias = (m == 0) ? ga.b0 : ((m == 1) ? ga.b1 : ga.b2);
    void* op          = (m == 0) ? ga.o0 : ((m == 1) ? ga.o1 : ga.o2);
    const bool q16    = (ga.i16mask >> m) & 1;

    #pragma unroll
    for (int mi = 0; mi < 2; mi++) {
        int rA = bm + mrow + mi * 16 + g;
        #pragma unroll
        for (int ni = 0; ni < 8; ni++) {
            int c = ncol + ni * 8 + q * 2;
            float bx = bias ? bias[c] : 0.f;
            float by = bias ? bias[c + 1] : 0.f;
            float2 v0, v1;
            v0.x = d[mi][ni][0] + bx;  v0.y = d[mi][ni][1] + by;
            v1.x = d[mi][ni][2] + bx;  v1.y = d[mi][ni][3] + by;
            if (RELU) {
                v0.x = fmaxf(v0.x, 0.f); v0.y = fmaxf(v0.y, 0.f);
                v1.x = fmaxf(v1.x, 0.f); v1.y = fmaxf(v1.y, 0.f);
            }
            if (q16) {
                short* os = (short*)op;
                int i0 = max(-32768, min(32767, __float2int_rn(v0.x * QSCALE)));
                int i1 = max(-32768, min(32767, __float2int_rn(v0.y * QSCALE)));
                int i2 = max(-32768, min(32767, __float2int_rn(v1.x * QSCALE)));
                int i3 = max(-32768, min(32767, __float2int_rn(v1.y * QSCALE)));
                *(uint32_t*)(os + (size_t)rA * 128 + c) =
                    (uint32_t)(i0 & 0xffff) | ((uint32_t)i1 << 16);
                *(uint32_t*)(os + (size_t)(rA + 8) * 128 + c) =
                    (uint32_t)(i2 & 0xffff) | ((uint32_t)i3 << 16);
            } else {
                float* of = (float*)op;
                *(float2*)(of + (size_t)rA * 128 + c)       = v0;
                *(float2*)(of + (size_t)(rA + 8) * 128 + c) = v1;
            }
        }
    }
}

// -------------------- attention: one warp per node ---------------------------
// int16 K/V/E tables (x4096); conflict-free sc[warp][l][head] layout.
__global__ void __launch_bounds__(256)
attn_kernel(const int* __restrict__ node_edges,
            const int* __restrict__ edge_nodes)
{
    __shared__ float sc[8][32][8];       // [warp][key l][head]
    const unsigned FULL = 0xffffffffu;
    int t = threadIdx.x & 31;
    int w = threadIdx.x >> 5;
    int n = blockIdx.x * 8 + w;

    int d = t >> 3, j = t & 7;
    int e = node_edges[n * DDN + d];
    int u = edge_nodes[e * KKN + j];

    float4 q = ((const float4*)(g_Q + (size_t)n * 128))[t];  // dims 4t..4t+3
    int g = t >> 2;                      // head of this lane's dims

    // edge term (x4096 units), once per edge
    float es[4];
    #pragma unroll
    for (int dd = 0; dd < 4; dd++) {
        int ee = __shfl_sync(FULL, e, dd * 8);
        uint2 r = ((const uint2*)(g_KWe16 + (size_t)ee * 128))[t];
        float f0 = (float)(short)r.x,        f1 = (float)((int)r.x >> 16);
        float f2 = (float)(short)r.y,        f3 = (float)((int)r.y >> 16);
        float p = fmaf(q.x, f0, fmaf(q.y, f1, fmaf(q.z, f2, q.w * f3)));
        p += __shfl_xor_sync(FULL, p, 1);
        p += __shfl_xor_sync(FULL, p, 2);
        es[dd] = p;
    }

    // node-key term
    #pragma unroll
    for (int l = 0; l < 32; l++) {
        int uu = __shfl_sync(FULL, u, l);
        uint2 r = ((const uint2*)(g_KWh16 + (size_t)uu * 128))[t];
        float f0 = (float)(short)r.x,        f1 = (float)((int)r.x >> 16);
        float f2 = (float)(short)r.y,        f3 = (float)((int)r.y >> 16);
        float p = fmaf(q.x, f0, fmaf(q.y, f1, fmaf(q.z, f2, q.w * f3)));
        p += __shfl_xor_sync(FULL, p, 1);
        p += __shfl_xor_sync(FULL, p, 2);
        if ((t & 3) == 0)
            sc[w][l][g] = (p + es[l >> 3]) * (0.25f * INV_QSCALE); // /sqrt(16)/4096
    }
    __syncwarp();

    // per-head softmax: 4-lane group g owns head g; lane r handles keys r+4i
    {
        int r = t & 3;
        float vv[8];
        float m = -1e30f;
        #pragma unroll
        for (int i = 0; i < 8; i++) { vv[i] = sc[w][r + i * 4][g]; m = fmaxf(m, vv[i]); }
        m = fmaxf(m, __shfl_xor_sync(FULL, m, 1));
        m = fmaxf(m, __shfl_xor_sync(FULL, m, 2));
        float s = 0.f;
        #pragma unroll
        for (int i = 0; i < 8; i++) { vv[i] = __expf(vv[i] - m); s += vv[i]; }
        s += __shfl_xor_sync(FULL, s, 1);
        s += __shfl_xor_sync(FULL, s, 2);
        float inv = 1.0f / s;
        #pragma unroll
        for (int i = 0; i < 8; i++) sc[w][r + i * 4][g] = vv[i] * inv;
    }
    __syncwarp();

    // context (v in x4096 units; rescale once at the end)
    float4 acc = make_float4(0.f, 0.f, 0.f, 0.f);
    #pragma unroll
    for (int l = 0; l < 32; l++) {
        int uu = __shfl_sync(FULL, u, l);
        float a = sc[w][l][g];
        uint2 r = ((const uint2*)(g_VWh16 + (size_t)uu * 128))[t];
        float f0 = (float)(short)r.x,        f1 = (float)((int)r.x >> 16);
        float f2 = (float)(short)r.y,        f3 = (float)((int)r.y >> 16);
        acc.x = fmaf(a, f0, acc.x);
        acc.y = fmaf(a, f1, acc.y);
        acc.z = fmaf(a, f2, acc.z);
        acc.w = fmaf(a, f3, acc.w);
    }
    acc.x *= INV_QSCALE; acc.y *= INV_QSCALE;
    acc.z *= INV_QSCALE; acc.w *= INV_QSCALE;
    ((float4*)(g_CTX + (size_t)n * 128))[t] = acc;
}

// -------------------- launch -------------------------------------------------
extern "C" void kernel_launch(void* const* d_in, const int* in_sizes, int n_in,
                              void* d_out, int out_size)
{
    const float* x          = (const float*)d_in[0];
    const float* edge_attr  = (const float*)d_in[1];
    const int*   node_edges = (const int*)  d_in[2];
    const int*   edge_nodes = (const int*)  d_in[3];
    const float* W_lin      = (const float*)d_in[4];
    const float* W_edge     = (const float*)d_in[5];
    const float* Wq         = (const float*)d_in[6];
    const float* Wk         = (const float*)d_in[7];
    const float* Wv         = (const float*)d_in[8];
    const float* bq         = (const float*)d_in[9];
    const float* bk         = (const float*)d_in[10];
    const float* bv         = (const float*)d_in[11];
    const float* Wo         = (const float*)d_in[12];
    const float* bo         = (const float*)d_in[13];
    float*       out        = (float*)d_out;

    int Nn = in_sizes[0] / HID;    // 32768
    int En = in_sizes[1] / EDIM;   // 16384

    float *pWc, *pWe, *pQ, *pCTX;
    short *pKWh16, *pVWh16, *pKWe16;
    cudaGetSymbolAddress((void**)&pWc,    g_Wc);
    cudaGetSymbolAddress((void**)&pWe,    g_We);
    cudaGetSymbolAddress((void**)&pQ,     g_Q);
    cudaGetSymbolAddress((void**)&pKWh16, g_KWh16);
    cudaGetSymbolAddress((void**)&pVWh16, g_VWh16);
    cudaGetSymbolAddress((void**)&pKWe16, g_KWe16);
    cudaGetSymbolAddress((void**)&pCTX,   g_CTX);

    const int SM128 = 4 * 128 * (128 / 2 + 4) * 4;   // 139264 B
    const int SM64  = 4 * 128 * (64 / 2 + 4) * 4;    //  73728 B
    cudaFuncSetAttribute(gemm_mma<128, false>, cudaFuncAttributeMaxDynamicSharedMemorySize, SM128);
    cudaFuncSetAttribute(gemm_mma<128, true>,  cudaFuncAttributeMaxDynamicSharedMemorySize, SM128);
    cudaFuncSetAttribute(gemm_mma<64, false>,  cudaFuncAttributeMaxDynamicSharedMemorySize, SM64);

    // K0: fold weights
    combine_w<<<dim3(128, 4), 128>>>(W_lin, W_edge, Wq, Wk, Wv);

    // K1: node projections, 3 matrices in parallel via blockIdx.y
    //     m=0: Q (fp32, +bq)   m=1: KWh (int16)   m=2: VWh (int16, +bv)
    {
        GemmArgs ga;
        ga.b0 = bq; ga.b1 = nullptr; ga.b2 = bv;
        ga.o0 = pQ; ga.o1 = pKWh16;  ga.o2 = pVWh16;
        ga.i16mask = 0b110;
        gemm_mma<128, false><<<dim3(Nn / 128, 3), 256, SM128>>>(x, pWc, ga);
    }

    // K2: edge projection  KWe = edge_attr @ (Wk W_edge)^T + bk  (int16)
    {
        GemmArgs ga;
        ga.b0 = bk; ga.b1 = nullptr; ga.b2 = nullptr;
        ga.o0 = pKWe16; ga.o1 = nullptr; ga.o2 = nullptr;
        ga.i16mask = 0b1;
        gemm_mma<64, false><<<dim3(En / 128, 1), 256, SM64>>>(edge_attr, pWe, ga);
    }

    // K3: attention -> ctx
    attn_kernel<<<Nn / 8, 256>>>(node_edges, edge_nodes);

    // K4: out = relu(ctx @ Wo^T + bo)
    {
        GemmArgs ga;
        ga.b0 = bo; ga.b1 = nullptr; ga.b2 = nullptr;
        ga.o0 = out; ga.o1 = nullptr; ga.o2 = nullptr;
        ga.i16mask = 0;
        gemm_mma<128, true><<<dim3(Nn / 128, 1), 256, SM128>>>(pCTX, Wo, ga);
    }
}

// round 16
// speedup vs baseline: 2.4415x; 1.2722x over previous
#include <cuda_runtime.h>
#include <cuda_fp16.h>
#include <cstdint>
#include <cstddef>

// Problem constants
#define NN   32768
#define EE   16384
#define DDN  4
#define KKN  8
#define HID  128
#define EDIM 64
#define NHD  8
#define LLK  32

#define QSCALE 4096.0f
#define INV_QSCALE (1.0f / 4096.0f)

// -------------------- scratch (device globals; no allocations) --------------
__device__ __half g_Wch[3 * 128 * 128];     // fp16 hi of Wq*Wlin, Wk*Wlin, Wv*Wlin
__device__ __half g_Wcl[3 * 128 * 128];     // fp16 lo residual
__device__ __half g_Weh[128 * 64];          // fp16 hi of Wk*W_edge
__device__ __half g_Wel[128 * 64];
__device__ __half g_Woh[128 * 128];         // fp16 hi of Wo
__device__ __half g_Wol[128 * 128];
__device__ __half g_x16[(size_t)NN * 128];  // fp16(x)
__device__ __half g_e16[(size_t)EE * 64];   // fp16(edge_attr)
__device__ float  g_Q[(size_t)NN * 128];    // fp32 queries
__device__ short  g_KWh16[(size_t)NN * 128];// int16 key-node table   (x4096)
__device__ short  g_VWh16[(size_t)NN * 128];// int16 value-node table (x4096)
__device__ short  g_KWe16[(size_t)EE * 128];// int16 key-edge table   (x4096)
__device__ __half g_CTX16[(size_t)NN * 128];// fp16 context (A of K4)

// -------------------- prep: fp32 -> fp16 ------------------------------------
__global__ void to_half(const float* __restrict__ src, __half* __restrict__ dst)
{
    int i = blockIdx.x * 256 + threadIdx.x;
    float4 v = ((const float4*)src)[i];
    __half2* d = (__half2*)dst;
    d[2 * i + 0] = __floats2half2_rn(v.x, v.y);
    d[2 * i + 1] = __floats2half2_rn(v.z, v.w);
}

// -------------------- K0: weight folding + fp16 hi/lo split -------------------
__global__ void combine_w(const float* __restrict__ Wlin,
                          const float* __restrict__ Wedge,
                          const float* __restrict__ Wq,
                          const float* __restrict__ Wk,
                          const float* __restrict__ Wv,
                          const float* __restrict__ Wo)
{
    int o = blockIdx.x, mat = blockIdx.y, i = threadIdx.x;
    if (mat < 3) {
        const float* Wt = (mat == 0) ? Wq : ((mat == 1) ? Wk : Wv);
        float s = 0.f;
        #pragma unroll 8
        for (int j = 0; j < 128; j++) s = fmaf(Wt[o * 128 + j], Wlin[j * 128 + i], s);
        __half h = __float2half(s);
        g_Wch[((size_t)mat * 128 + o) * 128 + i] = h;
        g_Wcl[((size_t)mat * 128 + o) * 128 + i] = __float2half(s - __half2float(h));
    } else if (mat == 3) {
        if (i < 64) {
            float s = 0.f;
            #pragma unroll 8
            for (int j = 0; j < 128; j++) s = fmaf(Wk[o * 128 + j], Wedge[j * 64 + i], s);
            __half h = __float2half(s);
            g_Weh[o * 64 + i] = h;
            g_Wel[o * 64 + i] = __float2half(s - __half2float(h));
        }
    } else {
        float s = Wo[o * 128 + i];
        __half h = __float2half(s);
        g_Woh[o * 128 + i] = h;
        g_Wol[o * 128 + i] = __float2half(s - __half2float(h));
    }
}

// -------------------- HMMA fp16 2-term GEMM ----------------------------------
// out_m[128,128] = act(A[*,KA] @ (Whi_m + Wlo_m)[128,KA]^T + bias_m)
// A already fp16; D = A*Bhi + A*Blo, fp32 accumulators.
// blockIdx.y = m. 256 threads, 2 CTAs/SM.

__device__ __forceinline__ void mma16816(float* d, const uint32_t* a,
                                         uint32_t b0, uint32_t b1)
{
    asm volatile(
        "mma.sync.aligned.m16n8k16.row.col.f32.f16.f16.f32 "
        "{%0,%1,%2,%3}, {%4,%5,%6,%7}, {%8,%9}, {%0,%1,%2,%3};"
        : "+f"(d[0]), "+f"(d[1]), "+f"(d[2]), "+f"(d[3])
        : "r"(a[0]), "r"(a[1]), "r"(a[2]), "r"(a[3]), "r"(b0), "r"(b1));
}

// copy 128 x KA halves into SMEM with row stride SW=KA/2+4 u32 (conflict-free)
template <int KA>
__device__ __forceinline__ void stage_copy(const __half* __restrict__ src,
                                           uint32_t* __restrict__ dst, int tid)
{
    constexpr int SW = KA / 2 + 4;
    constexpr int NQ = 128 * KA / 8;     // uint4 chunks
    #pragma unroll
    for (int idx = tid; idx < NQ; idx += 256) {
        int row = idx / (KA / 8);
        int qd  = idx % (KA / 8);
        uint4 v = *(const uint4*)(src + (size_t)row * KA + qd * 8);
        *(uint4*)(dst + row * SW + qd * 4) = v;
    }
}

struct GemmArgs {
    const float* b0; const float* b1; const float* b2;
    void* o0; void* o1; void* o2;
    int i16mask;   // bit m set -> output m stored as int16 * QSCALE
};

template <int KA, bool RELU>
__global__ void __launch_bounds__(256, 2)
gemm_mma(const __half* __restrict__ A,
         const __half* __restrict__ Whi, const __half* __restrict__ Wlo,
         GemmArgs ga)
{
    constexpr int SW  = KA / 2 + 4;
    constexpr int BUF = 128 * SW;
    constexpr int NSTEP = KA / 16;

    extern __shared__ uint32_t smem[];
    uint32_t* sA  = smem;
    uint32_t* sBh = smem + BUF;
    uint32_t* sBl = smem + 2 * BUF;

    const int tid  = threadIdx.x;
    const int w    = tid >> 5;
    const int lane = tid & 31;
    const int g    = lane >> 2;
    const int q    = lane & 3;
    const int bm   = blockIdx.x * 128;
    const int m    = blockIdx.y;
    const int mrow = (w & 3) * 32;
    const int ncol = (w >> 2) * 64;

    stage_copy<KA>(A + (size_t)bm * KA,       sA,  tid);
    stage_copy<KA>(Whi + (size_t)m * 128 * KA, sBh, tid);
    stage_copy<KA>(Wlo + (size_t)m * 128 * KA, sBl, tid);
    __syncthreads();

    float d[2][8][4];
    #pragma unroll
    for (int mi = 0; mi < 2; mi++)
        #pragma unroll
        for (int ni = 0; ni < 8; ni++)
            #pragma unroll
            for (int c = 0; c < 4; c++) d[mi][ni][c] = 0.f;

    #pragma unroll
    for (int k = 0; k < NSTEP; k++) {
        const int kp = k * 8;
        uint32_t a[2][4];
        #pragma unroll
        for (int mi = 0; mi < 2; mi++) {
            int r0 = (mrow + mi * 16 + g) * SW + kp + q;
            int r1 = r0 + 8 * SW;
            a[mi][0] = sA[r0];     a[mi][1] = sA[r1];
            a[mi][2] = sA[r0 + 4]; a[mi][3] = sA[r1 + 4];
        }
        #pragma unroll
        for (int ni = 0; ni < 8; ni++) {
            int cb = (ncol + ni * 8 + g) * SW + kp + q;
            uint32_t bh0 = sBh[cb], bh1 = sBh[cb + 4];
            uint32_t bl0 = sBl[cb], bl1 = sBl[cb + 4];
            #pragma unroll
            for (int mi = 0; mi < 2; mi++) {
                mma16816(d[mi][ni], a[mi], bh0, bh1);
                mma16816(d[mi][ni], a[mi], bl0, bl1);
            }
        }
    }

    // epilogue
    const float* bias = (m == 0) ? ga.b0 : ((m == 1) ? ga.b1 : ga.b2);
    void* op          = (m == 0) ? ga.o0 : ((m == 1) ? ga.o1 : ga.o2);
    const bool q16    = (ga.i16mask >> m) & 1;

    #pragma unroll
    for (int mi = 0; mi < 2; mi++) {
        int rA = bm + mrow + mi * 16 + g;
        #pragma unroll
        for (int ni = 0; ni < 8; ni++) {
            int c = ncol + ni * 8 + q * 2;
            float bx = bias ? bias[c] : 0.f;
            float by = bias ? bias[c + 1] : 0.f;
            float2 v0, v1;
            v0.x = d[mi][ni][0] + bx;  v0.y = d[mi][ni][1] + by;
            v1.x = d[mi][ni][2] + bx;  v1.y = d[mi][ni][3] + by;
            if (RELU) {
                v0.x = fmaxf(v0.x, 0.f); v0.y = fmaxf(v0.y, 0.f);
                v1.x = fmaxf(v1.x, 0.f); v1.y = fmaxf(v1.y, 0.f);
            }
            if (q16) {
                short* os = (short*)op;
                int i0 = max(-32768, min(32767, __float2int_rn(v0.x * QSCALE)));
                int i1 = max(-32768, min(32767, __float2int_rn(v0.y * QSCALE)));
                int i2 = max(-32768, min(32767, __float2int_rn(v1.x * QSCALE)));
                int i3 = max(-32768, min(32767, __float2int_rn(v1.y * QSCALE)));
                *(uint32_t*)(os + (size_t)rA * 128 + c) =
                    (uint32_t)(i0 & 0xffff) | ((uint32_t)i1 << 16);
                *(uint32_t*)(os + (size_t)(rA + 8) * 128 + c) =
                    (uint32_t)(i2 & 0xffff) | ((uint32_t)i3 << 16);
            } else {
                float* of = (float*)op;
                *(float2*)(of + (size_t)rA * 128 + c)       = v0;
                *(float2*)(of + (size_t)(rA + 8) * 128 + c) = v1;
            }
        }
    }
}

// -------------------- attention: one warp per node ---------------------------
// int16 K/V/E tables (x4096); ctx written as fp16 for the output GEMM.
__global__ void __launch_bounds__(256)
attn_kernel(const int* __restrict__ node_edges,
            const int* __restrict__ edge_nodes)
{
    __shared__ float sc[8][32][8];       // [warp][key l][head]
    const unsigned FULL = 0xffffffffu;
    int t = threadIdx.x & 31;
    int w = threadIdx.x >> 5;
    int n = blockIdx.x * 8 + w;

    int d = t >> 3, j = t & 7;
    int e = node_edges[n * DDN + d];
    int u = edge_nodes[e * KKN + j];

    // q pre-scaled by 1/sqrt(hd)/QSCALE: scores come out in final units
    float4 q = ((const float4*)(g_Q + (size_t)n * 128))[t];
    const float QS = 0.25f * INV_QSCALE;
    q.x *= QS; q.y *= QS; q.z *= QS; q.w *= QS;
    int g = t >> 2;

    // edge term, once per edge
    float es[4];
    #pragma unroll
    for (int dd = 0; dd < 4; dd++) {
        int ee = __shfl_sync(FULL, e, dd * 8);
        uint2 r = ((const uint2*)(g_KWe16 + (size_t)ee * 128))[t];
        float f0 = (float)(short)r.x,  f1 = (float)((int)r.x >> 16);
        float f2 = (float)(short)r.y,  f3 = (float)((int)r.y >> 16);
        float p = fmaf(q.x, f0, fmaf(q.y, f1, fmaf(q.z, f2, q.w * f3)));
        p += __shfl_xor_sync(FULL, p, 1);
        p += __shfl_xor_sync(FULL, p, 2);
        es[dd] = p;
    }

    // node-key term
    #pragma unroll
    for (int l = 0; l < 32; l++) {
        int uu = __shfl_sync(FULL, u, l);
        uint2 r = ((const uint2*)(g_KWh16 + (size_t)uu * 128))[t];
        float f0 = (float)(short)r.x,  f1 = (float)((int)r.x >> 16);
        float f2 = (float)(short)r.y,  f3 = (float)((int)r.y >> 16);
        float p = fmaf(q.x, f0, fmaf(q.y, f1, fmaf(q.z, f2, q.w * f3)));
        p += __shfl_xor_sync(FULL, p, 1);
        p += __shfl_xor_sync(FULL, p, 2);
        sc[w][l][g] = p + es[l >> 3];    // same value from all 4 lanes of head g
    }
    __syncwarp();

    // per-head softmax; fold the V int16 rescale into the normalizer
    {
        int r = t & 3;
        float vv[8];
        float m = -1e30f;
        #pragma unroll
        for (int i = 0; i < 8; i++) { vv[i] = sc[w][r + i * 4][g]; m = fmaxf(m, vv[i]); }
        m = fmaxf(m, __shfl_xor_sync(FULL, m, 1));
        m = fmaxf(m, __shfl_xor_sync(FULL, m, 2));
        float s = 0.f;
        #pragma unroll
        for (int i = 0; i < 8; i++) { vv[i] = __expf(vv[i] - m); s += vv[i]; }
        s += __shfl_xor_sync(FULL, s, 1);
        s += __shfl_xor_sync(FULL, s, 2);
        float inv = INV_QSCALE / s;
        #pragma unroll
        for (int i = 0; i < 8; i++) sc[w][r + i * 4][g] = vv[i] * inv;
    }
    __syncwarp();

    // context (weights already carry INV_QSCALE)
    float4 acc = make_float4(0.f, 0.f, 0.f, 0.f);
    #pragma unroll
    for (int l = 0; l < 32; l++) {
        int uu = __shfl_sync(FULL, u, l);
        float a = sc[w][l][g];
        uint2 r = ((const uint2*)(g_VWh16 + (size_t)uu * 128))[t];
        float f0 = (float)(short)r.x,  f1 = (float)((int)r.x >> 16);
        float f2 = (float)(short)r.y,  f3 = (float)((int)r.y >> 16);
        acc.x = fmaf(a, f0, acc.x);
        acc.y = fmaf(a, f1, acc.y);
        acc.z = fmaf(a, f2, acc.z);
        acc.w = fmaf(a, f3, acc.w);
    }
    __half2 h0 = __floats2half2_rn(acc.x, acc.y);
    __half2 h1 = __floats2half2_rn(acc.z, acc.w);
    uint2 pk;
    pk.x = *(uint32_t*)&h0;
    pk.y = *(uint32_t*)&h1;
    ((uint2*)(g_CTX16 + (size_t)n * 128))[t] = pk;
}

// -------------------- launch -------------------------------------------------
extern "C" void kernel_launch(void* const* d_in, const int* in_sizes, int n_in,
                              void* d_out, int out_size)
{
    const float* x          = (const float*)d_in[0];
    const float* edge_attr  = (const float*)d_in[1];
    const int*   node_edges = (const int*)  d_in[2];
    const int*   edge_nodes = (const int*)  d_in[3];
    const float* W_lin      = (const float*)d_in[4];
    const float* W_edge     = (const float*)d_in[5];
    const float* Wq         = (const float*)d_in[6];
    const float* Wk         = (const float*)d_in[7];
    const float* Wv         = (const float*)d_in[8];
    const float* bq         = (const float*)d_in[9];
    const float* bk         = (const float*)d_in[10];
    const float* bv         = (const float*)d_in[11];
    const float* Wo         = (const float*)d_in[12];
    const float* bo         = (const float*)d_in[13];
    float*       out        = (float*)d_out;

    int Nn = in_sizes[0] / HID;    // 32768
    int En = in_sizes[1] / EDIM;   // 16384

    __half *pWch, *pWcl, *pWeh, *pWel, *pWoh, *pWol, *px16, *pe16, *pCTX16;
    float *pQ;
    short *pKWh16, *pVWh16, *pKWe16;
    cudaGetSymbolAddress((void**)&pWch,   g_Wch);
    cudaGetSymbolAddress((void**)&pWcl,   g_Wcl);
    cudaGetSymbolAddress((void**)&pWeh,   g_Weh);
    cudaGetSymbolAddress((void**)&pWel,   g_Wel);
    cudaGetSymbolAddress((void**)&pWoh,   g_Woh);
    cudaGetSymbolAddress((void**)&pWol,   g_Wol);
    cudaGetSymbolAddress((void**)&px16,   g_x16);
    cudaGetSymbolAddress((void**)&pe16,   g_e16);
    cudaGetSymbolAddress((void**)&pQ,     g_Q);
    cudaGetSymbolAddress((void**)&pKWh16, g_KWh16);
    cudaGetSymbolAddress((void**)&pVWh16, g_VWh16);
    cudaGetSymbolAddress((void**)&pKWe16, g_KWe16);
    cudaGetSymbolAddress((void**)&pCTX16, g_CTX16);

    const int SM128 = 3 * 128 * (128 / 2 + 4) * 4;   // 104448 B
    const int SM64  = 3 * 128 * (64 / 2 + 4) * 4;    //  55296 B
    cudaFuncSetAttribute(gemm_mma<128, false>, cudaFuncAttributeMaxDynamicSharedMemorySize, SM128);
    cudaFuncSetAttribute(gemm_mma<128, true>,  cudaFuncAttributeMaxDynamicSharedMemorySize, SM128);
    cudaFuncSetAttribute(gemm_mma<64, false>,  cudaFuncAttributeMaxDynamicSharedMemorySize, SM64);

    // preps: x -> fp16, edge_attr -> fp16; weight folding + hi/lo split
    to_half<<<(Nn * HID / 4) / 256, 256>>>(x, px16);
    to_half<<<(En * EDIM / 4) / 256, 256>>>(edge_attr, pe16);
    combine_w<<<dim3(128, 5), 128>>>(W_lin, W_edge, Wq, Wk, Wv, Wo);

    // K1: node projections, 3 matrices via blockIdx.y
    //     m=0: Q (fp32, +bq)   m=1: KWh (int16)   m=2: VWh (int16, +bv)
    {
        GemmArgs ga;
        ga.b0 = bq; ga.b1 = nullptr; ga.b2 = bv;
        ga.o0 = pQ; ga.o1 = pKWh16;  ga.o2 = pVWh16;
        ga.i16mask = 0b110;
        gemm_mma<128, false><<<dim3(Nn / 128, 3), 256, SM128>>>(px16, pWch, pWcl, ga);
    }

    // K2: edge projection  KWe = edge_attr @ (Wk W_edge)^T + bk  (int16)
    {
        GemmArgs ga;
        ga.b0 = bk; ga.b1 = nullptr; ga.b2 = nullptr;
        ga.o0 = pKWe16; ga.o1 = nullptr; ga.o2 = nullptr;
        ga.i16mask = 0b1;
        gemm_mma<64, false><<<dim3(En / 128, 1), 256, SM64>>>(pe16, pWeh, pWel, ga);
    }

    // K3: attention -> ctx (fp16)
    attn_kernel<<<Nn / 8, 256>>>(node_edges, edge_nodes);

    // K4: out = relu(ctx @ Wo^T + bo)
    {
        GemmArgs ga;
        ga.b0 = bo; ga.b1 = nullptr; ga.b2 = nullptr;
        ga.o0 = out; ga.o1 = nullptr; ga.o2 = nullptr;
        ga.i16mask = 0;
        gemm_mma<128, true><<<dim3(Nn / 128, 1), 256, SM128>>>(pCTX16, pWoh, pWol, ga);
    }
}

// round 17
// speedup vs baseline: 2.4763x; 1.0142x over previous
#include <cuda_runtime.h>
#include <cuda_fp16.h>
#include <cstdint>
#include <cstddef>

// Problem constants
#define NN   32768
#define EE   16384
#define DDN  4
#define KKN  8
#define HID  128
#define EDIM 64
#define NHD  8
#define LLK  32

#define QSCALE 4096.0f
#define INV_QSCALE (1.0f / 4096.0f)

// -------------------- scratch (device globals; no allocations) --------------
__device__ __half g_Wch[3 * 128 * 128];     // fp16 hi of Wq*Wlin, Wk*Wlin, Wv*Wlin
__device__ __half g_Wcl[3 * 128 * 128];     // fp16 lo residual
__device__ __half g_Weh[128 * 64];          // fp16 hi of Wk*W_edge
__device__ __half g_Wel[128 * 64];
__device__ __half g_Woh[128 * 128];         // fp16 hi of Wo
__device__ __half g_Wol[128 * 128];
__device__ __half g_x16[(size_t)NN * 128];  // fp16(x)
__device__ __half g_e16[(size_t)EE * 64];   // fp16(edge_attr)
__device__ float  g_Q[(size_t)NN * 128];    // fp32 queries
__device__ short  g_KWh16[(size_t)NN * 128];// int16 key-node table   (x4096)
__device__ short  g_VWh16[(size_t)NN * 128];// int16 value-node table (x4096)
__device__ short  g_KWe16[(size_t)EE * 128];// int16 key-edge table   (x4096)
__device__ __half g_CTX16[(size_t)NN * 128];// fp16 context (A of K4)

// -------------------- prep: fp32 -> fp16 ------------------------------------
__global__ void to_half(const float* __restrict__ src, __half* __restrict__ dst)
{
    int i = blockIdx.x * 256 + threadIdx.x;
    float4 v = ((const float4*)src)[i];
    __half2* d = (__half2*)dst;
    d[2 * i + 0] = __floats2half2_rn(v.x, v.y);
    d[2 * i + 1] = __floats2half2_rn(v.z, v.w);
}

// -------------------- K0: weight folding + fp16 hi/lo split -------------------
__global__ void combine_w(const float* __restrict__ Wlin,
                          const float* __restrict__ Wedge,
                          const float* __restrict__ Wq,
                          const float* __restrict__ Wk,
                          const float* __restrict__ Wv,
                          const float* __restrict__ Wo)
{
    int o = blockIdx.x, mat = blockIdx.y, i = threadIdx.x;
    if (mat < 3) {
        const float* Wt = (mat == 0) ? Wq : ((mat == 1) ? Wk : Wv);
        float s = 0.f;
        #pragma unroll 8
        for (int j = 0; j < 128; j++) s = fmaf(Wt[o * 128 + j], Wlin[j * 128 + i], s);
        __half h = __float2half(s);
        g_Wch[((size_t)mat * 128 + o) * 128 + i] = h;
        g_Wcl[((size_t)mat * 128 + o) * 128 + i] = __float2half(s - __half2float(h));
    } else if (mat == 3) {
        if (i < 64) {
            float s = 0.f;
            #pragma unroll 8
            for (int j = 0; j < 128; j++) s = fmaf(Wk[o * 128 + j], Wedge[j * 64 + i], s);
            __half h = __float2half(s);
            g_Weh[o * 64 + i] = h;
            g_Wel[o * 64 + i] = __float2half(s - __half2float(h));
        }
    } else {
        float s = Wo[o * 128 + i];
        __half h = __float2half(s);
        g_Woh[o * 128 + i] = h;
        g_Wol[o * 128 + i] = __float2half(s - __half2float(h));
    }
}

// -------------------- HMMA fp16 2-term GEMM, ldmatrix fragment loads ---------
// out_m[128,128] = act(A[*,KA] @ (Whi_m + Wlo_m)[128,KA]^T + bias_m)
// D = A*Bhi + A*Blo, fp32 accumulators. blockIdx.y = m. 256 thr, 2 CTAs/SM.

__device__ __forceinline__ uint32_t smem_u32(const void* p) {
    uint32_t a;
    asm("{ .reg .u64 t; cvta.to.shared.u64 t, %1; cvt.u32.u64 %0, t; }" : "=r"(a) : "l"(p));
    return a;
}

__device__ __forceinline__ void ldsm4(uint32_t* r, uint32_t addr) {
    asm volatile("ldmatrix.sync.aligned.m8n8.x4.shared.b16 {%0,%1,%2,%3}, [%4];"
        : "=r"(r[0]), "=r"(r[1]), "=r"(r[2]), "=r"(r[3]) : "r"(addr));
}

__device__ __forceinline__ void mma16816(float* d, const uint32_t* a,
                                         uint32_t b0, uint32_t b1)
{
    asm volatile(
        "mma.sync.aligned.m16n8k16.row.col.f32.f16.f16.f32 "
        "{%0,%1,%2,%3}, {%4,%5,%6,%7}, {%8,%9}, {%0,%1,%2,%3};"
        : "+f"(d[0]), "+f"(d[1]), "+f"(d[2]), "+f"(d[3])
        : "r"(a[0]), "r"(a[1]), "r"(a[2]), "r"(a[3]), "r"(b0), "r"(b1));
}

// copy 128 x KA halves into SMEM with row stride SW=KA/2+4 u32 (conflict-free)
template <int KA>
__device__ __forceinline__ void stage_copy(const __half* __restrict__ src,
                                           uint32_t* __restrict__ dst, int tid)
{
    constexpr int SW = KA / 2 + 4;
    constexpr int NQ = 128 * KA / 8;     // uint4 chunks
    #pragma unroll
    for (int idx = tid; idx < NQ; idx += 256) {
        int row = idx / (KA / 8);
        int qd  = idx % (KA / 8);
        uint4 v = *(const uint4*)(src + (size_t)row * KA + qd * 8);
        *(uint4*)(dst + row * SW + qd * 4) = v;
    }
}

struct GemmArgs {
    const float* b0; const float* b1; const float* b2;
    void* o0; void* o1; void* o2;
    int i16mask;   // bit m set -> output m stored as int16 * QSCALE
};

template <int KA, bool RELU>
__global__ void __launch_bounds__(256, 2)
gemm_mma(const __half* __restrict__ A,
         const __half* __restrict__ Whi, const __half* __restrict__ Wlo,
         GemmArgs ga)
{
    constexpr int SW  = KA / 2 + 4;
    constexpr int BUF = 128 * SW;
    constexpr int NSTEP = KA / 16;

    extern __shared__ uint32_t smem[];
    uint32_t* sA  = smem;
    uint32_t* sBh = smem + BUF;
    uint32_t* sBl = smem + 2 * BUF;

    const int tid  = threadIdx.x;
    const int w    = tid >> 5;
    const int lane = tid & 31;
    const int g    = lane >> 2;
    const int q    = lane & 3;
    const int bm   = blockIdx.x * 128;
    const int m    = blockIdx.y;
    const int mrow = (w & 3) * 32;
    const int ncol = (w >> 2) * 64;

    stage_copy<KA>(A + (size_t)bm * KA,        sA,  tid);
    stage_copy<KA>(Whi + (size_t)m * 128 * KA, sBh, tid);
    stage_copy<KA>(Wlo + (size_t)m * 128 * KA, sBl, tid);
    __syncthreads();

    // ldmatrix per-lane base addresses (byte, shared space)
    const uint32_t su = smem_u32(smem);
    // A tiles: groups (rows+0,k0)(rows+8,k0)(rows+0,k8)(rows+8,k8)
    const int arow = mrow + ((lane >> 3) & 1) * 8 + (lane & 7);
    const int acol = ((lane >> 4) & 1) * 4;
    uint32_t aAddr[2];
    aAddr[0] = su + (((uint32_t)(arow * SW + acol)) << 2);
    aAddr[1] = aAddr[0] + ((uint32_t)(16 * SW) << 2);
    // B tiles (pair j -> ni=2j,2j+1): groups (n+0,k0)(n+0,k8)(n+8,k0)(n+8,k8)
    const int brow = ncol + ((lane >> 4) & 1) * 8 + (lane & 7);
    const int bcol = ((lane >> 3) & 1) * 4;
    uint32_t bAddrH[4], bAddrL[4];
    #pragma unroll
    for (int j = 0; j < 4; j++) {
        bAddrH[j] = su + ((uint32_t)(BUF + (brow + 16 * j) * SW + bcol) << 2);
        bAddrL[j] = bAddrH[j] + ((uint32_t)BUF << 2);
    }

    float d[2][8][4];
    #pragma unroll
    for (int mi = 0; mi < 2; mi++)
        #pragma unroll
        for (int ni = 0; ni < 8; ni++)
            #pragma unroll
            for (int c = 0; c < 4; c++) d[mi][ni][c] = 0.f;

    #pragma unroll
    for (int k = 0; k < NSTEP; k++) {
        const uint32_t ko = (uint32_t)k * 32u;   // 8 u32 per k-step
        uint32_t a[2][4];
        ldsm4(a[0], aAddr[0] + ko);
        ldsm4(a[1], aAddr[1] + ko);
        uint32_t bh[4][4], bl[4][4];
        #pragma unroll
        for (int j = 0; j < 4; j++) {
            ldsm4(bh[j], bAddrH[j] + ko);
            ldsm4(bl[j], bAddrL[j] + ko);
        }
        #pragma unroll
        for (int j = 0; j < 4; j++) {
            #pragma unroll
            for (int mi = 0; mi < 2; mi++) {
                mma16816(d[mi][2 * j + 0], a[mi], bh[j][0], bh[j][1]);
                mma16816(d[mi][2 * j + 0], a[mi], bl[j][0], bl[j][1]);
                mma16816(d[mi][2 * j + 1], a[mi], bh[j][2], bh[j][3]);
                mma16816(d[mi][2 * j + 1], a[mi], bl[j][2], bl[j][3]);
            }
        }
    }

    // epilogue
    const float* bias = (m == 0) ? ga.b0 : ((m == 1) ? ga.b1 : ga.b2);
    void* op          = (m == 0) ? ga.o0 : ((m == 1) ? ga.o1 : ga.o2);
    const bool q16    = (ga.i16mask >> m) & 1;

    #pragma unroll
    for (int mi = 0; mi < 2; mi++) {
        int rA = bm + mrow + mi * 16 + g;
        #pragma unroll
        for (int ni = 0; ni < 8; ni++) {
            int c = ncol + ni * 8 + q * 2;
            float bx = bias ? bias[c] : 0.f;
            float by = bias ? bias[c + 1] : 0.f;
            float2 v0, v1;
            v0.x = d[mi][ni][0] + bx;  v0.y = d[mi][ni][1] + by;
            v1.x = d[mi][ni][2] + bx;  v1.y = d[mi][ni][3] + by;
            if (RELU) {
                v0.x = fmaxf(v0.x, 0.f); v0.y = fmaxf(v0.y, 0.f);
                v1.x = fmaxf(v1.x, 0.f); v1.y = fmaxf(v1.y, 0.f);
            }
            if (q16) {
                short* os = (short*)op;
                int i0 = max(-32768, min(32767, __float2int_rn(v0.x * QSCALE)));
                int i1 = max(-32768, min(32767, __float2int_rn(v0.y * QSCALE)));
                int i2 = max(-32768, min(32767, __float2int_rn(v1.x * QSCALE)));
                int i3 = max(-32768, min(32767, __float2int_rn(v1.y * QSCALE)));
                *(uint32_t*)(os + (size_t)rA * 128 + c) =
                    (uint32_t)(i0 & 0xffff) | ((uint32_t)i1 << 16);
                *(uint32_t*)(os + (size_t)(rA + 8) * 128 + c) =
                    (uint32_t)(i2 & 0xffff) | ((uint32_t)i3 << 16);
            } else {
                float* of = (float*)op;
                *(float2*)(of + (size_t)rA * 128 + c)       = v0;
                *(float2*)(of + (size_t)(rA + 8) * 128 + c) = v1;
            }
        }
    }
}

// -------------------- attention: one warp per node ---------------------------
// int16 K/V/E tables (x4096); ctx written as fp16 for the output GEMM.
__global__ void __launch_bounds__(256)
attn_kernel(const int* __restrict__ node_edges,
            const int* __restrict__ edge_nodes)
{
    __shared__ float sc[8][32][8];       // [warp][key l][head]
    const unsigned FULL = 0xffffffffu;
    int t = threadIdx.x & 31;
    int w = threadIdx.x >> 5;
    int n = blockIdx.x * 8 + w;

    int d = t >> 3, j = t & 7;
    int e = node_edges[n * DDN + d];
    int u = edge_nodes[e * KKN + j];

    // q pre-scaled by 1/sqrt(hd)/QSCALE: scores come out in final units
    float4 q = ((const float4*)(g_Q + (size_t)n * 128))[t];
    const float QS = 0.25f * INV_QSCALE;
    q.x *= QS; q.y *= QS; q.z *= QS; q.w *= QS;
    int g = t >> 2;

    // edge term, once per edge
    float es[4];
    #pragma unroll
    for (int dd = 0; dd < 4; dd++) {
        int ee = __shfl_sync(FULL, e, dd * 8);
        uint2 r = ((const uint2*)(g_KWe16 + (size_t)ee * 128))[t];
        float f0 = (float)(short)r.x,  f1 = (float)((int)r.x >> 16);
        float f2 = (float)(short)r.y,  f3 = (float)((int)r.y >> 16);
        float p = fmaf(q.x, f0, fmaf(q.y, f1, fmaf(q.z, f2, q.w * f3)));
        p += __shfl_xor_sync(FULL, p, 1);
        p += __shfl_xor_sync(FULL, p, 2);
        es[dd] = p;
    }

    // node-key term
    #pragma unroll
    for (int l = 0; l < 32; l++) {
        int uu = __shfl_sync(FULL, u, l);
        uint2 r = ((const uint2*)(g_KWh16 + (size_t)uu * 128))[t];
        float f0 = (float)(short)r.x,  f1 = (float)((int)r.x >> 16);
        float f2 = (float)(short)r.y,  f3 = (float)((int)r.y >> 16);
        float p = fmaf(q.x, f0, fmaf(q.y, f1, fmaf(q.z, f2, q.w * f3)));
        p += __shfl_xor_sync(FULL, p, 1);
        p += __shfl_xor_sync(FULL, p, 2);
        sc[w][l][g] = p + es[l >> 3];    // same value from all 4 lanes of head g
    }
    __syncwarp();

    // per-head softmax; fold the V int16 rescale into the normalizer
    {
        int r = t & 3;
        float vv[8];
        float m = -1e30f;
        #pragma unroll
        for (int i = 0; i < 8; i++) { vv[i] = sc[w][r + i * 4][g]; m = fmaxf(m, vv[i]); }
        m = fmaxf(m, __shfl_xor_sync(FULL, m, 1));
        m = fmaxf(m, __shfl_xor_sync(FULL, m, 2));
        float s = 0.f;
        #pragma unroll
        for (int i = 0; i < 8; i++) { vv[i] = __expf(vv[i] - m); s += vv[i]; }
        s += __shfl_xor_sync(FULL, s, 1);
        s += __shfl_xor_sync(FULL, s, 2);
        float inv = INV_QSCALE / s;
        #pragma unroll
        for (int i = 0; i < 8; i++) sc[w][r + i * 4][g] = vv[i] * inv;
    }
    __syncwarp();

    // context (weights already carry INV_QSCALE)
    float4 acc = make_float4(0.f, 0.f, 0.f, 0.f);
    #pragma unroll
    for (int l = 0; l < 32; l++) {
        int uu = __shfl_sync(FULL, u, l);
        float a = sc[w][l][g];
        uint2 r = ((const uint2*)(g_VWh16 + (size_t)uu * 128))[t];
        float f0 = (float)(short)r.x,  f1 = (float)((int)r.x >> 16);
        float f2 = (float)(short)r.y,  f3 = (float)((int)r.y >> 16);
        acc.x = fmaf(a, f0, acc.x);
        acc.y = fmaf(a, f1, acc.y);
        acc.z = fmaf(a, f2, acc.z);
        acc.w = fmaf(a, f3, acc.w);
    }
    __half2 h0 = __floats2half2_rn(acc.x, acc.y);
    __half2 h1 = __floats2half2_rn(acc.z, acc.w);
    uint2 pk;
    pk.x = *(uint32_t*)&h0;
    pk.y = *(uint32_t*)&h1;
    ((uint2*)(g_CTX16 + (size_t)n * 128))[t] = pk;
}

// -------------------- launch -------------------------------------------------
extern "C" void kernel_launch(void* const* d_in, const int* in_sizes, int n_in,
                              void* d_out, int out_size)
{
    const float* x          = (const float*)d_in[0];
    const float* edge_attr  = (const float*)d_in[1];
    const int*   node_edges = (const int*)  d_in[2];
    const int*   edge_nodes = (const int*)  d_in[3];
    const float* W_lin      = (const float*)d_in[4];
    const float* W_edge     = (const float*)d_in[5];
    const float* Wq         = (const float*)d_in[6];
    const float* Wk         = (const float*)d_in[7];
    const float* Wv         = (const float*)d_in[8];
    const float* bq         = (const float*)d_in[9];
    const float* bk         = (const float*)d_in[10];
    const float* bv         = (const float*)d_in[11];
    const float* Wo         = (const float*)d_in[12];
    const float* bo         = (const float*)d_in[13];
    float*       out        = (float*)d_out;

    int Nn = in_sizes[0] / HID;    // 32768
    int En = in_sizes[1] / EDIM;   // 16384

    __half *pWch, *pWcl, *pWeh, *pWel, *pWoh, *pWol, *px16, *pe16, *pCTX16;
    float *pQ;
    short *pKWh16, *pVWh16, *pKWe16;
    cudaGetSymbolAddress((void**)&pWch,   g_Wch);
    cudaGetSymbolAddress((void**)&pWcl,   g_Wcl);
    cudaGetSymbolAddress((void**)&pWeh,   g_Weh);
    cudaGetSymbolAddress((void**)&pWel,   g_Wel);
    cudaGetSymbolAddress((void**)&pWoh,   g_Woh);
    cudaGetSymbolAddress((void**)&pWol,   g_Wol);
    cudaGetSymbolAddress((void**)&px16,   g_x16);
    cudaGetSymbolAddress((void**)&pe16,   g_e16);
    cudaGetSymbolAddress((void**)&pQ,     g_Q);
    cudaGetSymbolAddress((void**)&pKWh16, g_KWh16);
    cudaGetSymbolAddress((void**)&pVWh16, g_VWh16);
    cudaGetSymbolAddress((void**)&pKWe16, g_KWe16);
    cudaGetSymbolAddress((void**)&pCTX16, g_CTX16);

    const int SM128 = 3 * 128 * (128 / 2 + 4) * 4;   // 104448 B
    const int SM64  = 3 * 128 * (64 / 2 + 4) * 4;    //  55296 B
    cudaFuncSetAttribute(gemm_mma<128, false>, cudaFuncAttributeMaxDynamicSharedMemorySize, SM128);
    cudaFuncSetAttribute(gemm_mma<128, true>,  cudaFuncAttributeMaxDynamicSharedMemorySize, SM128);
    cudaFuncSetAttribute(gemm_mma<64, false>,  cudaFuncAttributeMaxDynamicSharedMemorySize, SM64);

    // preps: x -> fp16, edge_attr -> fp16; weight folding + hi/lo split
    to_half<<<(Nn * HID / 4) / 256, 256>>>(x, px16);
    to_half<<<(En * EDIM / 4) / 256, 256>>>(edge_attr, pe16);
    combine_w<<<dim3(128, 5), 128>>>(W_lin, W_edge, Wq, Wk, Wv, Wo);

    // K1: node projections, 3 matrices via blockIdx.y
    //     m=0: Q (fp32, +bq)   m=1: KWh (int16)   m=2: VWh (int16, +bv)
    {
        GemmArgs ga;
        ga.b0 = bq; ga.b1 = nullptr; ga.b2 = bv;
        ga.o0 = pQ; ga.o1 = pKWh16;  ga.o2 = pVWh16;
        ga.i16mask = 0b110;
        gemm_mma<128, false><<<dim3(Nn / 128, 3), 256, SM128>>>(px16, pWch, pWcl, ga);
    }

    // K2: edge projection  KWe = edge_attr @ (Wk W_edge)^T + bk  (int16)
    {
        GemmArgs ga;
        ga.b0 = bk; ga.b1 = nullptr; ga.b2 = nullptr;
        ga.o0 = pKWe16; ga.o1 = nullptr; ga.o2 = nullptr;
        ga.i16mask = 0b1;
        gemm_mma<64, false><<<dim3(En / 128, 1), 256, SM64>>>(pe16, pWeh, pWel, ga);
    }

    // K3: attention -> ctx (fp16)
    attn_kernel<<<Nn / 8, 256>>>(node_edges, edge_nodes);

    // K4: out = relu(ctx @ Wo^T + bo)
    {
        GemmArgs ga;
        ga.b0 = bo; ga.b1 = nullptr; ga.b2 = nullptr;
        ga.o0 = out; ga.o1 = nullptr; ga.o2 = nullptr;
        ga.i16mask = 0;
        gemm_mma<128, true><<<dim3(Nn / 128, 1), 256, SM128>>>(pCTX16, pWoh, pWol, ga);
    }
}